// round 6
// baseline (speedup 1.0000x reference)
#include <cuda_runtime.h>
#include <cuda_fp16.h>
#include <stdint.h>

#define NH 3
#define NB 16
#define NN 1024
#define NF 512
#define NFP 1024

// ---------------------------------------------------------------------------
// Scratch arena
// ---------------------------------------------------------------------------
#define OFF_XH    0ull            // x fp16            16 MB
#define OFF_KTH   16777216ull     // kernels^T fp16     3 MB
#define OFF_FTH   19922944ull     // feats^T fp16      96 MB
#define OFF_AH    120586240ull    // attn fp16         96 MB
#define OFF_W2S   221249536ull
#define OFF_W2N   221255680ull
#define OFF_SS    221261824ull
#define OFF_SN    221458432ull
#define OFF_BM    221655040ull
#define ARENA_SZ  221659136ull

__device__ __align__(128) unsigned char g_arena[ARENA_SZ];
#define AP(T, off) ((T*)(g_arena + (off)))

// ---------------------------------------------------------------------------
// PTX helpers (base sm_103 target)
// ---------------------------------------------------------------------------
__device__ __forceinline__ uint32_t smem_u32(const void* p) {
    uint32_t a;
    asm("{ .reg .u64 t; cvta.to.shared.u64 t, %1; cvt.u32.u64 %0, t; }"
        : "=r"(a) : "l"(p));
    return a;
}
__device__ __forceinline__ void cpasync16(uint32_t s, const void* g) {
    asm volatile("cp.async.cg.shared.global [%0], [%1], 16;"
                 :: "r"(s), "l"(g) : "memory");
}
__device__ __forceinline__ void cp_commit() {
    asm volatile("cp.async.commit_group;" ::: "memory");
}
template <int N>
__device__ __forceinline__ void cp_wait() {
    asm volatile("cp.async.wait_group %0;" :: "n"(N) : "memory");
}
__device__ __forceinline__ void ldsm4(uint32_t* r, uint32_t a) {
    asm volatile("ldmatrix.sync.aligned.m8n8.x4.shared.b16 {%0,%1,%2,%3}, [%4];"
                 : "=r"(r[0]), "=r"(r[1]), "=r"(r[2]), "=r"(r[3]) : "r"(a));
}
__device__ __forceinline__ void mma16816(float* c, const uint32_t* a,
                                         const uint32_t* b) {
    asm volatile(
        "mma.sync.aligned.m16n8k16.row.col.f32.f16.f16.f32 "
        "{%0,%1,%2,%3}, {%4,%5,%6,%7}, {%8,%9}, {%0,%1,%2,%3};"
        : "+f"(c[0]), "+f"(c[1]), "+f"(c[2]), "+f"(c[3])
        : "r"(a[0]), "r"(a[1]), "r"(a[2]), "r"(a[3]), "r"(b[0]), "r"(b[1]));
}

// ---------------------------------------------------------------------------
// GEMM core: CTA tile 256(M) x 128(N), kc=64, 256 threads (8 warps).
// Warp grid 4x2, warp tile 64x64 -> acc[4][8][4] (128 regs).
// Smem: A 256x144B + B 128x144B per stage (pitch-144 = conflict-free ldmatrix),
// 3-stage ring, one __syncthreads per stage.
// Per k16-step/warp: 8 LDSM : 32 HMMA.
// ---------------------------------------------------------------------------
#define GP_PITCH  144
#define A_TILE    36864        // 256 x 144
#define B_TILE    18432        // 128 x 144
#define G_STAGE   55296        // A + B
#define G_SMEM    165888       // 3 stages

__device__ __forceinline__ void ld_stage(
    uint32_t st, int tid, const __half* A, const __half* B, int lda, int ldb)
{
#pragma unroll
    for (int it = 0; it < 8; it++) {      // A: 256 rows x 8 segs
        const int idx = it * 256 + tid;
        const int row = idx >> 3, seg = idx & 7;
        cpasync16(st + row * GP_PITCH + seg * 16,
                  (const char*)(A + (size_t)row * lda) + seg * 16);
    }
#pragma unroll
    for (int it = 0; it < 4; it++) {      // B: 128 rows x 8 segs
        const int idx = it * 256 + tid;
        const int row = idx >> 3, seg = idx & 7;
        cpasync16(st + A_TILE + row * GP_PITCH + seg * 16,
                  (const char*)(B + (size_t)row * ldb) + seg * 16);
    }
    cp_commit();
}

// S = total kc-stages; KPH = stages per head; hst = per-head element stride.
template <int S, int KPH>
__device__ __forceinline__ void gemm_mma(
    const __half* A0, const __half* B0, size_t hst, int lda, int ldb,
    uint32_t sb, float acc[4][8][4], int wm, int wn, int lane, int tid)
{
#pragma unroll
    for (int mt = 0; mt < 4; mt++)
#pragma unroll
        for (int nt = 0; nt < 8; nt++)
#pragma unroll
            for (int q = 0; q < 4; q++) acc[mt][nt][q] = 0.f;

    ld_stage(sb,           tid, A0,      B0,      lda, ldb);
    ld_stage(sb + G_STAGE, tid, A0 + 64, B0 + 64, lda, ldb);

    for (int s = 0; s < S; s++) {
        if (s < S - 1) cp_wait<1>(); else cp_wait<0>();
        __syncthreads();
        const int sn = s + 2;
        if (sn < S) {
            const int hh = sn / KPH, kt = (sn % KPH) * 64;
            ld_stage(sb + (sn % 3) * G_STAGE, tid,
                     A0 + hh * hst + kt, B0 + hh * hst + kt, lda, ldb);
        }
        const uint32_t bu = sb + (s % 3) * G_STAGE;
        const uint32_t Ab = bu, Bb = bu + A_TILE;
#pragma unroll
        for (int ks = 0; ks < 4; ks++) {
            // B: 4 paired ldmatrix.x4, each serving two n-tiles' {k0,k8} frags.
            uint32_t bq[8][2];
            const int bcol = ks * 16 + (((lane >> 3) & 1) << 3);
            const int brow_in = ((lane >> 4) << 3) + (lane & 7);
#pragma unroll
            for (int p = 0; p < 4; p++) {
                uint32_t r[4];
                const int brow = wn * 64 + p * 16 + brow_in;
                ldsm4(r, Bb + (uint32_t)brow * GP_PITCH + bcol * 2);
                bq[2 * p][0] = r[0]; bq[2 * p][1] = r[1];
                bq[2 * p + 1][0] = r[2]; bq[2 * p + 1][1] = r[3];
            }
            const int arow = wm * 64 + (lane & 15);
            const int acol = ks * 16 + (lane >> 4) * 8;
#pragma unroll
            for (int mt = 0; mt < 4; mt++) {
                uint32_t aq[4];
                ldsm4(aq, Ab + (uint32_t)(arow + mt * 16) * GP_PITCH + acol * 2);
#pragma unroll
                for (int nt = 0; nt < 8; nt++)
                    mma16816(acc[mt][nt], aq, bq[nt]);
            }
        }
    }
}

// ---------------------------------------------------------------------------
// feats GEMM: D[fp][node] = sum_f kT[fp][f] * x[node][f]   (single fp16)
// M = fp (256-tile), N = node (128-tile)
// ---------------------------------------------------------------------------
__global__ void __launch_bounds__(256, 1) feats_tc() {
    extern __shared__ char dynsm[];
    const int tid = threadIdx.x;
    const int w = tid >> 5, lane = tid & 31;
    const int wm = w >> 1, wn = w & 1;
    const int z = blockIdx.z, h = z >> 4, b = z & 15;
    const int m0 = blockIdx.y * 256, n0 = blockIdx.x * 128;

    const __half* A0 = AP(__half, OFF_KTH) + (size_t)h * NFP * NF + (size_t)m0 * NF;
    const __half* B0 = AP(__half, OFF_XH)  + (size_t)b * NN * NF + (size_t)n0 * NF;

    float acc[4][8][4];
    gemm_mma<8, 8>(A0, B0, 0, NF, NF, smem_u32(dynsm), acc, wm, wn, lane, tid);

    __half* ft = AP(__half, OFF_FTH) + (size_t)z * NFP * NN;
#pragma unroll
    for (int mt = 0; mt < 4; mt++)
#pragma unroll
        for (int nt = 0; nt < 8; nt++)
#pragma unroll
            for (int hf = 0; hf < 2; hf++) {
                const int row = m0 + wm * 64 + mt * 16 + (lane >> 2) + hf * 8;
                const int col = n0 + wn * 64 + nt * 8 + (lane & 3) * 2;
                __half2 p;
                p.x = __float2half(acc[mt][nt][hf * 2 + 0]);
                p.y = __float2half(acc[mt][nt][hf * 2 + 1]);
                *(__half2*)(ft + (size_t)row * NN + col) = p;
            }
}

// ---------------------------------------------------------------------------
// out GEMM: D[node][fp] = sum_h sum_j attn[h,b,node,j] * fT[h,b][fp][j]
// M = node (256-tile), N = fp (128-tile)
// ---------------------------------------------------------------------------
__global__ void __launch_bounds__(256, 1) out_tc(float* __restrict__ out) {
    extern __shared__ char dynsm[];
    const int tid = threadIdx.x;
    const int w = tid >> 5, lane = tid & 31;
    const int wm = w >> 1, wn = w & 1;
    const int b = blockIdx.z;
    const int m0 = blockIdx.y * 256;   // node tile
    const int n0 = blockIdx.x * 128;   // fp tile

    const size_t hst = (size_t)NB * NN * NN;
    const __half* A0 = AP(__half, OFF_AH)  + ((size_t)b * NN + m0) * NN;
    const __half* B0 = AP(__half, OFF_FTH) + ((size_t)b * NFP + n0) * NN;

    float acc[4][8][4];
    gemm_mma<48, 16>(A0, B0, hst, NN, NN, smem_u32(dynsm), acc, wm, wn, lane, tid);

    const float* bm = AP(float, OFF_BM);
    float* C = out + ((size_t)(NH * NB) + b) * NN * NN;
#pragma unroll
    for (int mt = 0; mt < 4; mt++)
#pragma unroll
        for (int nt = 0; nt < 8; nt++)
#pragma unroll
            for (int hf = 0; hf < 2; hf++) {
                const int row = m0 + wm * 64 + mt * 16 + (lane >> 2) + hf * 8;
                const int col = n0 + wn * 64 + nt * 8 + (lane & 3) * 2;
                float2 v;
                v.x = acc[mt][nt][hf * 2 + 0] * (1.f / 3.f) + bm[col + 0];
                v.y = acc[mt][nt][hf * 2 + 1] * (1.f / 3.f) + bm[col + 1];
                *(float2*)(C + (size_t)row * NN + col) = v;
            }
}

// ---------------------------------------------------------------------------
// Prep kernels
// ---------------------------------------------------------------------------
__global__ void prep_x(const float* __restrict__ x) {
    const size_t i = (size_t)blockIdx.x * 256 + threadIdx.x;  // NB*NN*NF/4
    float4 v = ((const float4*)x)[i];
    union { __half h[4]; uint2 u; } o;
    o.h[0] = __float2half(v.x); o.h[1] = __float2half(v.y);
    o.h[2] = __float2half(v.z); o.h[3] = __float2half(v.w);
    ((uint2*)AP(unsigned char, OFF_XH))[i] = o.u;
}

// kernels (H, F, F_) -> kT (H, F_, F) fp16
__global__ void prep_kT(const float* __restrict__ kern) {
    __shared__ float t[32][33];
    const int h = blockIdx.z;
    const int fp0 = blockIdx.x * 32, f0 = blockIdx.y * 32;
    const float* src = kern + (size_t)h * NF * NFP;
#pragma unroll
    for (int j = 0; j < 4; j++)
        t[threadIdx.y + j * 8][threadIdx.x] =
            src[(size_t)(f0 + threadIdx.y + j * 8) * NFP + fp0 + threadIdx.x];
    __syncthreads();
    __half* dst = AP(__half, OFF_KTH) + (size_t)h * NFP * NF;
#pragma unroll
    for (int j = 0; j < 4; j++) {
        float v = t[threadIdx.x][threadIdx.y + j * 8];
        dst[(size_t)(fp0 + threadIdx.y + j * 8) * NF + f0 + threadIdx.x] =
            __float2half(v);
    }
}

// w2[h][f] = sum_fp kernels[h][f][fp] * a[h][fp]
__global__ void w2k(const float* __restrict__ kern,
                    const float* __restrict__ as, const float* __restrict__ an) {
    const int gw = blockIdx.x * 8 + (threadIdx.x >> 5);
    const int lane = threadIdx.x & 31;
    const int h = gw >> 9, f = gw & 511;
    const float* row = kern + ((size_t)h * NF + f) * NFP;
    const float* a1 = as + (size_t)h * NFP;
    const float* a2 = an + (size_t)h * NFP;
    float s1 = 0.f, s2 = 0.f;
#pragma unroll
    for (int it = 0; it < 8; it++) {
        int k = it * 128 + lane * 4;
        float4 kv = *(const float4*)(row + k);
        float4 v1 = *(const float4*)(a1 + k);
        float4 v2 = *(const float4*)(a2 + k);
        s1 += kv.x * v1.x + kv.y * v1.y + kv.z * v1.z + kv.w * v1.w;
        s2 += kv.x * v2.x + kv.y * v2.y + kv.z * v2.z + kv.w * v2.w;
    }
#pragma unroll
    for (int o = 16; o > 0; o >>= 1) {
        s1 += __shfl_xor_sync(0xFFFFFFFFu, s1, o);
        s2 += __shfl_xor_sync(0xFFFFFFFFu, s2, o);
    }
    if (lane == 0) {
        AP(float, OFF_W2S)[(size_t)h * NF + f] = s1;
        AP(float, OFF_W2N)[(size_t)h * NF + f] = s2;
    }
}

// s_self[h,b,n] = x[b,n,:] . w2s[h]; s_neigh likewise
__global__ void __launch_bounds__(256) s_comp(const float* __restrict__ x) {
    __shared__ float ws[NH * NF], wn_[NH * NF];
    for (int i = threadIdx.x; i < NH * NF; i += 256) {
        ws[i]  = AP(float, OFF_W2S)[i];
        wn_[i] = AP(float, OFF_W2N)[i];
    }
    __syncthreads();
    const int gw = blockIdx.x * 8 + (threadIdx.x >> 5);
    const int lane = threadIdx.x & 31;
    const int b = gw >> 10, n = gw & 1023;
    const float* xr = x + ((size_t)b * NN + n) * NF;
    float a[3] = {0.f, 0.f, 0.f}, c[3] = {0.f, 0.f, 0.f};
#pragma unroll
    for (int it = 0; it < 4; it++) {
        int f = it * 128 + lane * 4;
        float4 xv = *(const float4*)(xr + f);
#pragma unroll
        for (int h = 0; h < 3; h++) {
            float4 w = *(const float4*)&ws[h * NF + f];
            float4 u = *(const float4*)&wn_[h * NF + f];
            a[h] += xv.x * w.x + xv.y * w.y + xv.z * w.z + xv.w * w.w;
            c[h] += xv.x * u.x + xv.y * u.y + xv.z * u.z + xv.w * u.w;
        }
    }
#pragma unroll
    for (int h = 0; h < 3; h++) {
#pragma unroll
        for (int o = 16; o > 0; o >>= 1) {
            a[h] += __shfl_xor_sync(0xFFFFFFFFu, a[h], o);
            c[h] += __shfl_xor_sync(0xFFFFFFFFu, c[h], o);
        }
    }
    if (lane == 0) {
#pragma unroll
        for (int h = 0; h < 3; h++) {
            AP(float, OFF_SS)[(size_t)h * NB * NN + b * NN + n] = a[h];
            AP(float, OFF_SN)[(size_t)h * NB * NN + b * NN + n] = c[h];
        }
    }
}

// Row softmax of leaky(s_self[i]+s_neigh[j]); fp32 attn to d_out + fp16 copy.
__global__ void __launch_bounds__(256) attn_softmax(float* __restrict__ out) {
    __shared__ float c[NN];
    const int w    = threadIdx.x >> 5;
    const int lane = threadIdx.x & 31;
    const size_t r0 = (size_t)blockIdx.x * 8;
    const size_t hb = r0 >> 10;
    const float* cn = AP(float, OFF_SN) + hb * NN;
    for (int i = threadIdx.x; i < NN; i += 256) c[i] = cn[i];
    __syncthreads();

    const size_t r = r0 + w;
    const float a = AP(float, OFF_SS)[r];

    float ev[32];
    float m = -1e30f;
#pragma unroll
    for (int it = 0; it < 32; it++) {
        float t = a + c[it * 32 + lane];
        t = (t >= 0.f) ? t : 0.2f * t;
        ev[it] = t;
        m = fmaxf(m, t);
    }
#pragma unroll
    for (int o = 16; o > 0; o >>= 1) m = fmaxf(m, __shfl_xor_sync(0xFFFFFFFFu, m, o));
    float s = 0.f;
#pragma unroll
    for (int it = 0; it < 32; it++) {
        float e = __expf(ev[it] - m);
        ev[it] = e;
        s += e;
    }
#pragma unroll
    for (int o = 16; o > 0; o >>= 1) s += __shfl_xor_sync(0xFFFFFFFFu, s, o);
    const float inv = 1.f / s;

    float* orow = out + r * NN;
    __half* ah = AP(__half, OFF_AH) + r * NN;
#pragma unroll
    for (int it = 0; it < 32; it++) {
        float v = ev[it] * inv;
        int col = it * 32 + lane;
        orow[col] = v;
        ah[col] = __float2half(v);
    }
}

__global__ void bias_mean(const float* __restrict__ biases) {
    int k = blockIdx.x * 256 + threadIdx.x;
    AP(float, OFF_BM)[k] =
        (biases[k] + biases[NFP + k] + biases[2 * NFP + k]) * (1.f / 3.f);
}

// ---------------------------------------------------------------------------
extern "C" void kernel_launch(void* const* d_in, const int* in_sizes, int n_in,
                              void* d_out, int out_size)
{
    const float* x      = (const float*)d_in[0];
    const float* kern   = (const float*)d_in[1];
    const float* biases = (const float*)d_in[2];
    const float* aself  = (const float*)d_in[3];
    const float* aneigh = (const float*)d_in[4];
    float* out = (float*)d_out;

    cudaFuncSetAttribute(feats_tc, cudaFuncAttributeMaxDynamicSharedMemorySize, G_SMEM);
    cudaFuncSetAttribute(out_tc,   cudaFuncAttributeMaxDynamicSharedMemorySize, G_SMEM);

    prep_x<<<(NB * NN * NF / 4) / 256, 256>>>(x);
    prep_kT<<<dim3(NFP / 32, NF / 32, NH), dim3(32, 8)>>>(kern);
    w2k<<<(NH * NF) / 8, 256>>>(kern, aself, aneigh);
    s_comp<<<(NB * NN) / 8, 256>>>(x);
    attn_softmax<<<(NH * NB * NN) / 8, 256>>>(out);
    bias_mean<<<NFP / 256, 256>>>(biases);

    feats_tc<<<dim3(NN / 128, NFP / 256, NH * NB), 256, G_SMEM>>>();
    out_tc<<<dim3(NFP / 128, NN / 256, NB), 256, G_SMEM>>>(out);
}

// round 7
// speedup vs baseline: 1.1758x; 1.1758x over previous
#include <cuda_runtime.h>
#include <cuda_fp16.h>
#include <stdint.h>

#define NH 3
#define NB 16
#define NN 1024
#define NF 512
#define NFP 1024

// ---------------------------------------------------------------------------
// Scratch arena
// ---------------------------------------------------------------------------
#define OFF_XH    0ull            // x fp16            16 MB
#define OFF_KTH   16777216ull     // kernels^T fp16     3 MB
#define OFF_FTH   19922944ull     // feats^T fp16      96 MB
#define OFF_AH    120586240ull    // attn fp16         96 MB
#define OFF_W2S   221249536ull
#define OFF_W2N   221255680ull
#define OFF_SS    221261824ull
#define OFF_SN    221458432ull
#define OFF_BM    221655040ull
#define ARENA_SZ  221659136ull

__device__ __align__(128) unsigned char g_arena[ARENA_SZ];
#define AP(T, off) ((T*)(g_arena + (off)))

// ---------------------------------------------------------------------------
// PTX helpers (base sm_103 target)
// ---------------------------------------------------------------------------
__device__ __forceinline__ uint32_t smem_u32(const void* p) {
    uint32_t a;
    asm("{ .reg .u64 t; cvta.to.shared.u64 t, %1; cvt.u32.u64 %0, t; }"
        : "=r"(a) : "l"(p));
    return a;
}
__device__ __forceinline__ void cpasync16(uint32_t s, const void* g) {
    asm volatile("cp.async.cg.shared.global [%0], [%1], 16;"
                 :: "r"(s), "l"(g) : "memory");
}
__device__ __forceinline__ void cp_commit() {
    asm volatile("cp.async.commit_group;" ::: "memory");
}
template <int N>
__device__ __forceinline__ void cp_wait() {
    asm volatile("cp.async.wait_group %0;" :: "n"(N) : "memory");
}
__device__ __forceinline__ void ldsm4(uint32_t* r, uint32_t a) {
    asm volatile("ldmatrix.sync.aligned.m8n8.x4.shared.b16 {%0,%1,%2,%3}, [%4];"
                 : "=r"(r[0]), "=r"(r[1]), "=r"(r[2]), "=r"(r[3]) : "r"(a));
}
__device__ __forceinline__ void mma16816(float* c, const uint32_t* a,
                                         const uint32_t* b) {
    asm volatile(
        "mma.sync.aligned.m16n8k16.row.col.f32.f16.f16.f32 "
        "{%0,%1,%2,%3}, {%4,%5,%6,%7}, {%8,%9}, {%0,%1,%2,%3};"
        : "+f"(c[0]), "+f"(c[1]), "+f"(c[2]), "+f"(c[3])
        : "r"(a[0]), "r"(a[1]), "r"(a[2]), "r"(a[3]), "r"(b[0]), "r"(b[1]));
}

// ---------------------------------------------------------------------------
// Unified GEMM core (R5 config, proven): 128x128 CTA tile, kc=64, fp16 K-major.
// 2 tiles/stage, 144B pitch, 3-stage ring, 1 sync/stage, 2 CTAs/SM.
// Warp tile 64x32 (2x4 warp grid), B fragments fetched pairwise via ldmatrix.x4.
// ---------------------------------------------------------------------------
#define GP_PITCH  144
#define G_TILE    18432        // 128 x 144
#define G_STAGE   36864        // 2 tiles
#define G_SMEM    110592       // 3 stages

__device__ __forceinline__ void ld_stage(
    uint32_t st, int tid, const __half* A, const __half* B, int lda, int ldb)
{
#pragma unroll
    for (int it = 0; it < 4; it++) {
        const int idx = it * 256 + tid;
        const int row = idx >> 3, seg = idx & 7;
        const uint32_t so = row * GP_PITCH + seg * 16;
        cpasync16(st + so,          (const char*)(A + (size_t)row * lda) + seg * 16);
        cpasync16(st + G_TILE + so, (const char*)(B + (size_t)row * ldb) + seg * 16);
    }
    cp_commit();
}

// S = total kc-stages; KPH = stages per head; hst = per-head element stride.
template <int S, int KPH>
__device__ __forceinline__ void gemm_mma(
    const __half* A0, const __half* B0, size_t hst, int lda, int ldb,
    uint32_t sb, float acc[4][4][4], int wm, int wn, int lane, int tid)
{
#pragma unroll
    for (int mt = 0; mt < 4; mt++)
#pragma unroll
        for (int nt = 0; nt < 4; nt++)
#pragma unroll
            for (int q = 0; q < 4; q++) acc[mt][nt][q] = 0.f;

    ld_stage(sb,           tid, A0,      B0,      lda, ldb);
    ld_stage(sb + G_STAGE, tid, A0 + 64, B0 + 64, lda, ldb);

    for (int s = 0; s < S; s++) {
        if (s < S - 1) cp_wait<1>(); else cp_wait<0>();
        __syncthreads();
        const int sn = s + 2;
        if (sn < S) {
            const int hh = sn / KPH, kt = (sn % KPH) * 64;
            ld_stage(sb + (sn % 3) * G_STAGE, tid,
                     A0 + hh * hst + kt, B0 + hh * hst + kt, lda, ldb);
        }
        const uint32_t bu = sb + (s % 3) * G_STAGE;
        const uint32_t Ab = bu, Bb = bu + G_TILE;
#pragma unroll
        for (int ks = 0; ks < 4; ks++) {
            // B: two ldmatrix.x4, each serving two n-tiles' {k0,k8} fragments.
            uint32_t bq[4][2];
            const int bcol = ks * 16 + (((lane >> 3) & 1) << 3);
            const int brow_in = ((lane >> 4) << 3) + (lane & 7);
#pragma unroll
            for (int p = 0; p < 2; p++) {
                uint32_t r[4];
                const int brow = wn * 32 + p * 16 + brow_in;
                ldsm4(r, Bb + (uint32_t)brow * GP_PITCH + bcol * 2);
                bq[2 * p][0] = r[0]; bq[2 * p][1] = r[1];
                bq[2 * p + 1][0] = r[2]; bq[2 * p + 1][1] = r[3];
            }
            const int arow = wm * 64 + (lane & 15);
            const int acol = ks * 16 + (lane >> 4) * 8;
#pragma unroll
            for (int mt = 0; mt < 4; mt++) {
                uint32_t aq[4];
                ldsm4(aq, Ab + (uint32_t)(arow + mt * 16) * GP_PITCH + acol * 2);
#pragma unroll
                for (int nt = 0; nt < 4; nt++)
                    mma16816(acc[mt][nt], aq, bq[nt]);
            }
        }
    }
}

// ---------------------------------------------------------------------------
// feats GEMM: D[fp][node] = sum_f kT[fp][f] * x[node][f]   (single fp16)
// ---------------------------------------------------------------------------
__global__ void __launch_bounds__(256, 2) feats_tc() {
    extern __shared__ char dynsm[];
    const int tid = threadIdx.x;
    const int w = tid >> 5, lane = tid & 31;
    const int wm = w & 1, wn = w >> 1;
    const int z = blockIdx.z, h = z >> 4, b = z & 15;
    const int m0 = blockIdx.y * 128, n0 = blockIdx.x * 128;

    const __half* A0 = AP(__half, OFF_KTH) + (size_t)h * NFP * NF + (size_t)m0 * NF;
    const __half* B0 = AP(__half, OFF_XH)  + (size_t)b * NN * NF + (size_t)n0 * NF;

    float acc[4][4][4];
    gemm_mma<8, 8>(A0, B0, 0, NF, NF, smem_u32(dynsm), acc, wm, wn, lane, tid);

    __half* ft = AP(__half, OFF_FTH) + (size_t)z * NFP * NN;
#pragma unroll
    for (int mt = 0; mt < 4; mt++)
#pragma unroll
        for (int nt = 0; nt < 4; nt++)
#pragma unroll
            for (int hf = 0; hf < 2; hf++) {
                const int row = m0 + wm * 64 + mt * 16 + (lane >> 2) + hf * 8;
                const int col = n0 + wn * 32 + nt * 8 + (lane & 3) * 2;
                __half2 p;
                p.x = __float2half(acc[mt][nt][hf * 2 + 0]);
                p.y = __float2half(acc[mt][nt][hf * 2 + 1]);
                *(__half2*)(ft + (size_t)row * NN + col) = p;
            }
}

// ---------------------------------------------------------------------------
// out GEMM: D[node][fp] = sum_h sum_j attn[h,b,node,j] * fT[h,b][fp][j]
// ---------------------------------------------------------------------------
__global__ void __launch_bounds__(256, 2) out_tc(float* __restrict__ out) {
    extern __shared__ char dynsm[];
    const int tid = threadIdx.x;
    const int w = tid >> 5, lane = tid & 31;
    const int wm = w & 1, wn = w >> 1;
    const int b = blockIdx.z;
    const int m0 = blockIdx.y * 128;   // node tile
    const int n0 = blockIdx.x * 128;   // fp tile

    const size_t hst = (size_t)NB * NN * NN;
    const __half* A0 = AP(__half, OFF_AH)  + ((size_t)b * NN + m0) * NN;
    const __half* B0 = AP(__half, OFF_FTH) + ((size_t)b * NFP + n0) * NN;

    float acc[4][4][4];
    gemm_mma<48, 16>(A0, B0, hst, NN, NN, smem_u32(dynsm), acc, wm, wn, lane, tid);

    const float* bm = AP(float, OFF_BM);
    float* C = out + ((size_t)(NH * NB) + b) * NN * NN;
#pragma unroll
    for (int mt = 0; mt < 4; mt++)
#pragma unroll
        for (int nt = 0; nt < 4; nt++)
#pragma unroll
            for (int hf = 0; hf < 2; hf++) {
                const int row = m0 + wm * 64 + mt * 16 + (lane >> 2) + hf * 8;
                const int col = n0 + wn * 32 + nt * 8 + (lane & 3) * 2;
                float2 v;
                v.x = acc[mt][nt][hf * 2 + 0] * (1.f / 3.f) + bm[col + 0];
                v.y = acc[mt][nt][hf * 2 + 1] * (1.f / 3.f) + bm[col + 1];
                *(float2*)(C + (size_t)row * NN + col) = v;
            }
}

// ---------------------------------------------------------------------------
// Prep kernels
// ---------------------------------------------------------------------------
__global__ void prep_x(const float* __restrict__ x) {
    const size_t i = (size_t)blockIdx.x * 256 + threadIdx.x;  // NB*NN*NF/4
    float4 v = ((const float4*)x)[i];
    union { __half h[4]; uint2 u; } o;
    o.h[0] = __float2half(v.x); o.h[1] = __float2half(v.y);
    o.h[2] = __float2half(v.z); o.h[3] = __float2half(v.w);
    ((uint2*)AP(unsigned char, OFF_XH))[i] = o.u;
}

// kernels (H, F, F_) -> kT (H, F_, F) fp16
__global__ void prep_kT(const float* __restrict__ kern) {
    __shared__ float t[32][33];
    const int h = blockIdx.z;
    const int fp0 = blockIdx.x * 32, f0 = blockIdx.y * 32;
    const float* src = kern + (size_t)h * NF * NFP;
#pragma unroll
    for (int j = 0; j < 4; j++)
        t[threadIdx.y + j * 8][threadIdx.x] =
            src[(size_t)(f0 + threadIdx.y + j * 8) * NFP + fp0 + threadIdx.x];
    __syncthreads();
    __half* dst = AP(__half, OFF_KTH) + (size_t)h * NFP * NF;
#pragma unroll
    for (int j = 0; j < 4; j++) {
        float v = t[threadIdx.x][threadIdx.y + j * 8];
        dst[(size_t)(fp0 + threadIdx.y + j * 8) * NF + f0 + threadIdx.x] =
            __float2half(v);
    }
}

// w2[h][f] = sum_fp kernels[h][f][fp] * a[h][fp]
__global__ void w2k(const float* __restrict__ kern,
                    const float* __restrict__ as, const float* __restrict__ an) {
    const int gw = blockIdx.x * 8 + (threadIdx.x >> 5);
    const int lane = threadIdx.x & 31;
    const int h = gw >> 9, f = gw & 511;
    const float* row = kern + ((size_t)h * NF + f) * NFP;
    const float* a1 = as + (size_t)h * NFP;
    const float* a2 = an + (size_t)h * NFP;
    float s1 = 0.f, s2 = 0.f;
#pragma unroll
    for (int it = 0; it < 8; it++) {
        int k = it * 128 + lane * 4;
        float4 kv = *(const float4*)(row + k);
        float4 v1 = *(const float4*)(a1 + k);
        float4 v2 = *(const float4*)(a2 + k);
        s1 += kv.x * v1.x + kv.y * v1.y + kv.z * v1.z + kv.w * v1.w;
        s2 += kv.x * v2.x + kv.y * v2.y + kv.z * v2.z + kv.w * v2.w;
    }
#pragma unroll
    for (int o = 16; o > 0; o >>= 1) {
        s1 += __shfl_xor_sync(0xFFFFFFFFu, s1, o);
        s2 += __shfl_xor_sync(0xFFFFFFFFu, s2, o);
    }
    if (lane == 0) {
        AP(float, OFF_W2S)[(size_t)h * NF + f] = s1;
        AP(float, OFF_W2N)[(size_t)h * NF + f] = s2;
    }
}

// s_self[h,b,n] = x[b,n,:] . w2s[h]; s_neigh likewise
__global__ void __launch_bounds__(256) s_comp(const float* __restrict__ x) {
    __shared__ float ws[NH * NF], wn_[NH * NF];
    for (int i = threadIdx.x; i < NH * NF; i += 256) {
        ws[i]  = AP(float, OFF_W2S)[i];
        wn_[i] = AP(float, OFF_W2N)[i];
    }
    __syncthreads();
    const int gw = blockIdx.x * 8 + (threadIdx.x >> 5);
    const int lane = threadIdx.x & 31;
    const int b = gw >> 10, n = gw & 1023;
    const float* xr = x + ((size_t)b * NN + n) * NF;
    float a[3] = {0.f, 0.f, 0.f}, c[3] = {0.f, 0.f, 0.f};
#pragma unroll
    for (int it = 0; it < 4; it++) {
        int f = it * 128 + lane * 4;
        float4 xv = *(const float4*)(xr + f);
#pragma unroll
        for (int h = 0; h < 3; h++) {
            float4 w = *(const float4*)&ws[h * NF + f];
            float4 u = *(const float4*)&wn_[h * NF + f];
            a[h] += xv.x * w.x + xv.y * w.y + xv.z * w.z + xv.w * w.w;
            c[h] += xv.x * u.x + xv.y * u.y + xv.z * u.z + xv.w * u.w;
        }
    }
#pragma unroll
    for (int h = 0; h < 3; h++) {
#pragma unroll
        for (int o = 16; o > 0; o >>= 1) {
            a[h] += __shfl_xor_sync(0xFFFFFFFFu, a[h], o);
            c[h] += __shfl_xor_sync(0xFFFFFFFFu, c[h], o);
        }
    }
    if (lane == 0) {
#pragma unroll
        for (int h = 0; h < 3; h++) {
            AP(float, OFF_SS)[(size_t)h * NB * NN + b * NN + n] = a[h];
            AP(float, OFF_SN)[(size_t)h * NB * NN + b * NN + n] = c[h];
        }
    }
}

// Row softmax of leaky(s_self[i]+s_neigh[j]); fp32 attn to d_out + fp16 copy.
__global__ void __launch_bounds__(256) attn_softmax(float* __restrict__ out) {
    __shared__ float c[NN];
    const int w    = threadIdx.x >> 5;
    const int lane = threadIdx.x & 31;
    const size_t r0 = (size_t)blockIdx.x * 8;
    const size_t hb = r0 >> 10;
    const float* cn = AP(float, OFF_SN) + hb * NN;
    for (int i = threadIdx.x; i < NN; i += 256) c[i] = cn[i];
    __syncthreads();

    const size_t r = r0 + w;
    const float a = AP(float, OFF_SS)[r];

    float ev[32];
    float m = -1e30f;
#pragma unroll
    for (int it = 0; it < 32; it++) {
        float t = a + c[it * 32 + lane];
        t = (t >= 0.f) ? t : 0.2f * t;
        ev[it] = t;
        m = fmaxf(m, t);
    }
#pragma unroll
    for (int o = 16; o > 0; o >>= 1) m = fmaxf(m, __shfl_xor_sync(0xFFFFFFFFu, m, o));
    float s = 0.f;
#pragma unroll
    for (int it = 0; it < 32; it++) {
        float e = __expf(ev[it] - m);
        ev[it] = e;
        s += e;
    }
#pragma unroll
    for (int o = 16; o > 0; o >>= 1) s += __shfl_xor_sync(0xFFFFFFFFu, s, o);
    const float inv = 1.f / s;

    float* orow = out + r * NN;
    __half* ah = AP(__half, OFF_AH) + r * NN;
#pragma unroll
    for (int it = 0; it < 32; it++) {
        float v = ev[it] * inv;
        int col = it * 32 + lane;
        orow[col] = v;
        ah[col] = __float2half(v);
    }
}

__global__ void bias_mean(const float* __restrict__ biases) {
    int k = blockIdx.x * 256 + threadIdx.x;
    AP(float, OFF_BM)[k] =
        (biases[k] + biases[NFP + k] + biases[2 * NFP + k]) * (1.f / 3.f);
}

// ---------------------------------------------------------------------------
// Launch: fork the scalar branch (w2k -> s_comp -> attn_softmax, bias_mean)
// onto a side stream so it overlaps with prep_x/prep_kT/feats_tc.
// Stream/event objects are created lazily on the first (uncaptured) call and
// reused; every call enqueues the identical DAG, so capture + replay see the
// same deterministic work.
// ---------------------------------------------------------------------------
extern "C" void kernel_launch(void* const* d_in, const int* in_sizes, int n_in,
                              void* d_out, int out_size)
{
    const float* x      = (const float*)d_in[0];
    const float* kern   = (const float*)d_in[1];
    const float* biases = (const float*)d_in[2];
    const float* aself  = (const float*)d_in[3];
    const float* aneigh = (const float*)d_in[4];
    float* out = (float*)d_out;

    static cudaStream_t s1 = nullptr;
    static cudaEvent_t efork = nullptr, ejoin = nullptr;
    static bool attr_done = false;
    if (s1 == nullptr) {
        cudaStreamCreateWithFlags(&s1, cudaStreamNonBlocking);
        cudaEventCreateWithFlags(&efork, cudaEventDisableTiming);
        cudaEventCreateWithFlags(&ejoin, cudaEventDisableTiming);
    }
    if (!attr_done) {
        cudaFuncSetAttribute(feats_tc, cudaFuncAttributeMaxDynamicSharedMemorySize, G_SMEM);
        cudaFuncSetAttribute(out_tc,   cudaFuncAttributeMaxDynamicSharedMemorySize, G_SMEM);
        attr_done = true;
    }

    // Fork
    cudaEventRecord(efork, 0);
    cudaStreamWaitEvent(s1, efork, 0);

    // Branch B (side stream): logits chain + bias mean
    w2k<<<(NH * NF) / 8, 256, 0, s1>>>(kern, aself, aneigh);
    s_comp<<<(NB * NN) / 8, 256, 0, s1>>>(x);
    attn_softmax<<<(NH * NB * NN) / 8, 256, 0, s1>>>(out);
    bias_mean<<<NFP / 256, 256, 0, s1>>>(biases);

    // Branch A (main stream): fp16 prep + feats GEMM
    prep_x<<<(NB * NN * NF / 4) / 256, 256>>>(x);
    prep_kT<<<dim3(NFP / 32, NF / 32, NH), dim3(32, 8)>>>(kern);
    feats_tc<<<dim3(NN / 128, NFP / 128, NH * NB), 256, G_SMEM>>>();

    // Join, then the output GEMM (needs both branches)
    cudaEventRecord(ejoin, s1);
    cudaStreamWaitEvent(0, ejoin, 0);
    out_tc<<<dim3(NFP / 128, NN / 128, NB), 256, G_SMEM>>>(out);
}